// round 7
// baseline (speedup 1.0000x reference)
#include <cuda_runtime.h>
#include <cstdint>

#define Cn 16
#define Hn 512
#define Wn 512
#define HWn (Hn*Wn)
#define NSTEPS 8
#define GRIDX 152
#define NTHREADS 512
#define NTILES 2048
#define RS  132
#define W1S 84
#define W2S 132
#define HS  132

// ---- smem offsets (floats) ----
#define OFF_W1H 0
#define OFF_W1L (OFF_W1H + 128*W1S)        // 10752
#define OFF_W2H (OFF_W1L + 128*W1S)        // 21504
#define OFF_W2L (OFF_W2H + 16*W2S)         // 23616
#define OFF_B1  (OFF_W2L + 16*W2S)         // 25728
#define OFF_B2  (OFF_B1 + 128)             // 25856
#define OFF_R0  (OFF_B2 + 16)              // 25872
#define OFF_R1  (OFF_R0 + Cn*3*RS)         // 32208
#define OFF_H   (OFF_R1 + Cn*3*RS)         // 38544
#define SMEM_FLOATS (OFF_H + 128*HS)       // 55440 -> 221760 B

__device__ float g_bufA[Cn*HWn];
__device__ float g_bufB[Cn*HWn];
__device__ float g_w1h[128*W1S];
__device__ float g_w1l[128*W1S];
__device__ float g_w2h[16*W2S];
__device__ float g_w2l[16*W2S];

__device__ __forceinline__ uint32_t tf32h(float x) {
    uint32_t u;
    asm("cvt.rna.tf32.f32 %0, %1;" : "=r"(u) : "f"(x));
    return u;
}
__device__ __forceinline__ uint32_t smem_u32(const void* p) {
    uint32_t a;
    asm("{ .reg .u64 t; cvta.to.shared.u64 t, %1; cvt.u32.u64 %0, t; }" : "=r"(a) : "l"(p));
    return a;
}
__device__ __forceinline__ void cpa4(uint32_t d, const float* g) {
    asm volatile("cp.async.ca.shared.global [%0], [%1], 4;" :: "r"(d), "l"(g));
}
#define CP_COMMIT() asm volatile("cp.async.commit_group;" ::: "memory")
#define CP_WAIT0()  asm volatile("cp.async.wait_group 0;" ::: "memory")

__device__ __forceinline__ void mma8(float* d,
    uint32_t a0, uint32_t a1, uint32_t a2, uint32_t a3,
    uint32_t b0, uint32_t b1)
{
    asm volatile(
        "mma.sync.aligned.m16n8k8.row.col.f32.tf32.tf32.f32 "
        "{%0,%1,%2,%3}, {%4,%5,%6,%7}, {%8,%9}, {%0,%1,%2,%3};"
        : "+f"(d[0]), "+f"(d[1]), "+f"(d[2]), "+f"(d[3])
        : "r"(a0), "r"(a1), "r"(a2), "r"(a3), "r"(b0), "r"(b1));
}

// ---- weight pre-split + relayout ----
__global__ void w_setup(const float* __restrict__ W1, const float* __restrict__ W2) {
    int t = threadIdx.x;
    for (int i = t; i < 80*128; i += 256) {
        int k = i >> 7, n = i & 127;
        float v = W1[i];
        float hi = __uint_as_float(tf32h(v));
        g_w1h[n*W1S + k] = hi;
        g_w1l[n*W1S + k] = v - hi;
    }
    for (int i = t; i < 128*16; i += 256) {
        int k = i >> 4, n = i & 15;
        float v = W2[i];
        float hi = __uint_as_float(tf32h(v));
        g_w2h[n*W2S + k] = hi;
        g_w2l[n*W2S + k] = v - hi;
    }
}

// stage 48 row-segments (16ch x 3 rows) of tile (y,x0) into rows buffer at rb
__device__ __forceinline__ void stage_tile(const float* __restrict__ src,
                                           uint32_t sbase, int rb,
                                           int y, int x0, int w, int lane)
{
    const int ym = (y == 0)    ? 0 : (y - 1);
    const int yp = (y == Hn-1) ? 0 : (y + 1);
    #pragma unroll 1
    for (int s = w; s < 48; s += 16) {
        int c  = s / 3;
        int ri = s - c*3;
        int gy = (ri == 0) ? ym : ((ri == 1) ? y : yp);
        const float* gsrc = src + c*HWn + gy*Wn;
        uint32_t dbase = sbase + (uint32_t)(rb + s*RS) * 4u;
        #pragma unroll
        for (int j0 = 0; j0 < 160; j0 += 32) {
            int j = j0 + lane;
            if (j < 130) {
                int gx = x0 - 1 + j;
                gx = (gx < 0)   ? 0 : gx;     // clamp low edge
                gx = (gx >= Wn) ? 0 : gx;     // wrap high edge
                cpa4(dbase + 4u*j, gsrc + gx);
            }
        }
    }
}

__global__ void __launch_bounds__(NTHREADS, 1)
slime_step_mma(const float* __restrict__ src, float* __restrict__ dst,
               const float* __restrict__ gb1, const float* __restrict__ gb2)
{
    extern __shared__ float sm[];
    const uint32_t sbase = smem_u32(sm);
    const int tid = threadIdx.x;
    const int w = tid >> 5, lane = tid & 31;
    const int gr = lane >> 2, q = lane & 3;

    // ---- prologue: weights + biases to SMEM ----
    {
        float4* d; const float4* s;
        d = (float4*)(sm + OFF_W1H); s = (const float4*)g_w1h;
        for (int i = tid; i < 128*W1S/4; i += NTHREADS) d[i] = s[i];
        d = (float4*)(sm + OFF_W1L); s = (const float4*)g_w1l;
        for (int i = tid; i < 128*W1S/4; i += NTHREADS) d[i] = s[i];
        d = (float4*)(sm + OFF_W2H); s = (const float4*)g_w2h;
        for (int i = tid; i < 16*W2S/4; i += NTHREADS) d[i] = s[i];
        d = (float4*)(sm + OFF_W2L); s = (const float4*)g_w2l;
        for (int i = tid; i < 16*W2S/4; i += NTHREADS) d[i] = s[i];
        if (tid < 128) sm[OFF_B1 + tid] = gb1[tid];
        if (tid < 16)  sm[OFF_B2 + tid] = gb2[tid];
    }

    // ---- tile-invariant A-fragment offsets (relative to rows base) ----
    int foA[20];
    #pragma unroll
    for (int kc = 0; kc < 10; kc++)
        #pragma unroll
        for (int s2 = 0; s2 < 2; s2++) {
            int k = kc*8 + q + 4*s2;
            int dd = k >> 4, c = k & 15;
            int ri = (dd == 1) ? 0 : ((dd == 2) ? 2 : 1);
            int dx = (dd == 3) ? -1 : ((dd == 4) ? 1 : 0);
            foA[kc*2 + s2] = (c*3 + ri)*RS + 1 + dx;
        }

    // GEMM1 warp tile: 32 rows x 32 cols
    const int R0 = (w & 3) * 32, C0 = (w >> 2) * 32;
    // GEMM2 warp tile: 16 rows x 8 cols
    const int R2 = (w >> 1) * 16, C2 = (w & 1) * 8;

    const float* W1hp = sm + OFF_W1H;
    const float* W1lp = sm + OFF_W1L;
    const float* W2hp = sm + OFF_W2H;
    const float* W2lp = sm + OFF_W2L;
    const float* b1s  = sm + OFF_B1;
    const float* b2s  = sm + OFF_B2;
    float* Hs = sm + OFF_H;

    const int t0 = blockIdx.x;

    // ---- stage first tile into buffer 0 ----
    if (t0 < NTILES)
        stage_tile(src, sbase, OFF_R0, t0 >> 2, (t0 & 3) << 7, w, lane);
    CP_COMMIT();
    CP_WAIT0();
    __syncthreads();

    int pb = 0;
    for (int t = t0; t < NTILES; t += GRIDX) {
        const int y = t >> 2, x0 = (t & 3) << 7;
        const int rb  = pb ? OFF_R1 : OFF_R0;
        const int rbn = pb ? OFF_R0 : OFF_R1;
        const float* rcur = sm + rb;

        // ---- prefetch next tile's rows (overlaps with compute below) ----
        const int tn = t + GRIDX;
        if (tn < NTILES)
            stage_tile(src, sbase, rbn, tn >> 2, (tn & 3) << 7, w, lane);
        CP_COMMIT();

        // ================= GEMM1: D1 = X @ W1 (+b1), 3xtf32 =================
        float acc[2][4][4];
        #pragma unroll
        for (int nt = 0; nt < 4; nt++) {
            float bz0 = b1s[C0 + nt*8 + 2*q];
            float bz1 = b1s[C0 + nt*8 + 2*q + 1];
            #pragma unroll
            for (int mt = 0; mt < 2; mt++) {
                acc[mt][nt][0] = bz0; acc[mt][nt][1] = bz1;
                acc[mt][nt][2] = bz0; acc[mt][nt][3] = bz1;
            }
        }
        #pragma unroll
        for (int kc = 0; kc < 10; kc++) {
            uint32_t ah[2][4], al[2][4];
            #pragma unroll
            for (int mt = 0; mt < 2; mt++) {
                int r = R0 + mt*16 + gr;
                float v0 = rcur[foA[kc*2+0] + r];
                float v1 = rcur[foA[kc*2+0] + r + 8];
                float v2 = rcur[foA[kc*2+1] + r];
                float v3 = rcur[foA[kc*2+1] + r + 8];
                ah[mt][0] = tf32h(v0); al[mt][0] = __float_as_uint(v0 - __uint_as_float(ah[mt][0]));
                ah[mt][1] = tf32h(v1); al[mt][1] = __float_as_uint(v1 - __uint_as_float(ah[mt][1]));
                ah[mt][2] = tf32h(v2); al[mt][2] = __float_as_uint(v2 - __uint_as_float(ah[mt][2]));
                ah[mt][3] = tf32h(v3); al[mt][3] = __float_as_uint(v3 - __uint_as_float(ah[mt][3]));
            }
            uint32_t bh[4][2], bl[4][2];
            #pragma unroll
            for (int nt = 0; nt < 4; nt++) {
                int n = C0 + nt*8 + gr;
                bh[nt][0] = __float_as_uint(W1hp[n*W1S + kc*8 + q]);
                bh[nt][1] = __float_as_uint(W1hp[n*W1S + kc*8 + q + 4]);
                bl[nt][0] = __float_as_uint(W1lp[n*W1S + kc*8 + q]);
                bl[nt][1] = __float_as_uint(W1lp[n*W1S + kc*8 + q + 4]);
            }
            // term-major: dependent MMAs on same acc spaced 8 apart
            #pragma unroll
            for (int nt = 0; nt < 4; nt++)
                #pragma unroll
                for (int mt = 0; mt < 2; mt++)
                    mma8(acc[mt][nt], ah[mt][0], ah[mt][1], ah[mt][2], ah[mt][3], bh[nt][0], bh[nt][1]);
            #pragma unroll
            for (int nt = 0; nt < 4; nt++)
                #pragma unroll
                for (int mt = 0; mt < 2; mt++)
                    mma8(acc[mt][nt], al[mt][0], al[mt][1], al[mt][2], al[mt][3], bh[nt][0], bh[nt][1]);
            #pragma unroll
            for (int nt = 0; nt < 4; nt++)
                #pragma unroll
                for (int mt = 0; mt < 2; mt++)
                    mma8(acc[mt][nt], ah[mt][0], ah[mt][1], ah[mt][2], ah[mt][3], bl[nt][0], bl[nt][1]);
        }
        // ---- epilogue: H = relu(D1) ----
        #pragma unroll
        for (int mt = 0; mt < 2; mt++) {
            int r = R0 + mt*16 + gr;
            #pragma unroll
            for (int nt = 0; nt < 4; nt++) {
                int c = C0 + nt*8 + 2*q;
                float2 v0 = make_float2(fmaxf(acc[mt][nt][0], 0.0f), fmaxf(acc[mt][nt][1], 0.0f));
                float2 v1 = make_float2(fmaxf(acc[mt][nt][2], 0.0f), fmaxf(acc[mt][nt][3], 0.0f));
                *(float2*)&Hs[r*HS + c]     = v0;
                *(float2*)&Hs[(r+8)*HS + c] = v1;
            }
        }
        __syncthreads();

        // ================= GEMM2: D2 = H @ W2 (+b2), 3xtf32, local K-split =================
        float da[4], db[4];
        {
            float bz0 = b2s[C2 + 2*q], bz1 = b2s[C2 + 2*q + 1];
            da[0] = bz0; da[1] = bz1; da[2] = bz0; da[3] = bz1;
            db[0] = 0.f; db[1] = 0.f; db[2] = 0.f; db[3] = 0.f;
        }
        #pragma unroll
        for (int kp = 0; kp < 8; kp++) {
            // two independent K-chunks: kc_a = kp, kc_b = kp + 8
            uint32_t aah[4], aal[4], bah[4], bal[4];
            {
                int r = R2 + gr;
                float v0 = Hs[r*HS     + kp*8 + q];
                float v1 = Hs[(r+8)*HS + kp*8 + q];
                float v2 = Hs[r*HS     + kp*8 + q + 4];
                float v3 = Hs[(r+8)*HS + kp*8 + q + 4];
                aah[0] = tf32h(v0); aal[0] = __float_as_uint(v0 - __uint_as_float(aah[0]));
                aah[1] = tf32h(v1); aal[1] = __float_as_uint(v1 - __uint_as_float(aah[1]));
                aah[2] = tf32h(v2); aal[2] = __float_as_uint(v2 - __uint_as_float(aah[2]));
                aah[3] = tf32h(v3); aal[3] = __float_as_uint(v3 - __uint_as_float(aah[3]));
                float w0 = Hs[r*HS     + (kp+8)*8 + q];
                float w1 = Hs[(r+8)*HS + (kp+8)*8 + q];
                float w2 = Hs[r*HS     + (kp+8)*8 + q + 4];
                float w3 = Hs[(r+8)*HS + (kp+8)*8 + q + 4];
                bah[0] = tf32h(w0); bal[0] = __float_as_uint(w0 - __uint_as_float(bah[0]));
                bah[1] = tf32h(w1); bal[1] = __float_as_uint(w1 - __uint_as_float(bah[1]));
                bah[2] = tf32h(w2); bal[2] = __float_as_uint(w2 - __uint_as_float(bah[2]));
                bah[3] = tf32h(w3); bal[3] = __float_as_uint(w3 - __uint_as_float(bah[3]));
            }
            int n = C2 + gr;
            uint32_t wh0a = __float_as_uint(W2hp[n*W2S + kp*8 + q]);
            uint32_t wh1a = __float_as_uint(W2hp[n*W2S + kp*8 + q + 4]);
            uint32_t wl0a = __float_as_uint(W2lp[n*W2S + kp*8 + q]);
            uint32_t wl1a = __float_as_uint(W2lp[n*W2S + kp*8 + q + 4]);
            uint32_t wh0b = __float_as_uint(W2hp[n*W2S + (kp+8)*8 + q]);
            uint32_t wh1b = __float_as_uint(W2hp[n*W2S + (kp+8)*8 + q + 4]);
            uint32_t wl0b = __float_as_uint(W2lp[n*W2S + (kp+8)*8 + q]);
            uint32_t wl1b = __float_as_uint(W2lp[n*W2S + (kp+8)*8 + q + 4]);
            // interleave the two independent chains
            mma8(da, aah[0], aah[1], aah[2], aah[3], wh0a, wh1a);
            mma8(db, bah[0], bah[1], bah[2], bah[3], wh0b, wh1b);
            mma8(da, aal[0], aal[1], aal[2], aal[3], wh0a, wh1a);
            mma8(db, bal[0], bal[1], bal[2], bal[3], wh0b, wh1b);
            mma8(da, aah[0], aah[1], aah[2], aah[3], wl0a, wl1a);
            mma8(db, bah[0], bah[1], bah[2], bah[3], wl0b, wl1b);
        }

        // ---- output: s + delta (channel 0 snapshot-restored) ----
        {
            int px0  = R2 + gr;
            int pix0 = y*Wn + x0 + px0;
            #pragma unroll
            for (int jj = 0; jj < 4; jj++) {
                int c   = C2 + 2*q + (jj & 1);
                int px  = px0  + ((jj >= 2) ? 8 : 0);
                int pix = pix0 + ((jj >= 2) ? 8 : 0);
                float center = rcur[(c*3 + 1)*RS + 1 + px];
                float vout = (c == 0) ? center : (center + da[jj] + db[jj]);
                dst[c*HWn + pix] = vout;
            }
        }

        // prefetch done + H fully consumed before next tile
        CP_WAIT0();
        __syncthreads();
        pb ^= 1;
    }
}

extern "C" void kernel_launch(void* const* d_in, const int* in_sizes, int n_in,
                              void* d_out, int out_size)
{
    const float* state = (const float*)d_in[0];
    const float* W1    = (const float*)d_in[1];
    const float* b1    = (const float*)d_in[2];
    const float* W2    = (const float*)d_in[3];
    const float* b2    = (const float*)d_in[4];
    float* out = (float*)d_out;

    cudaFuncSetAttribute(slime_step_mma,
                         cudaFuncAttributeMaxDynamicSharedMemorySize,
                         SMEM_FLOATS * (int)sizeof(float));

    float *bufA, *bufB;
    cudaGetSymbolAddress((void**)&bufA, g_bufA);
    cudaGetSymbolAddress((void**)&bufB, g_bufB);

    w_setup<<<1, 256>>>(W1, W2);

    const float* cur = state;
    for (int s = 0; s < NSTEPS; s++) {
        float* dstp = (s == NSTEPS-1) ? out : ((s & 1) ? bufB : bufA);
        slime_step_mma<<<GRIDX, NTHREADS, SMEM_FLOATS*sizeof(float)>>>(cur, dstp, b1, b2);
        cur = dstp;
    }
}

// round 9
// speedup vs baseline: 1.6331x; 1.6331x over previous
#include <cuda_runtime.h>
#include <cstdint>

#define Cn 16
#define Hn 512
#define Wn 512
#define HWn (Hn*Wn)
#define NSTEPS 8
#define GRIDX 152
#define NTHREADS 256
#define NTILES 2048
#define RS  132
#define HS  132

// ---- smem float offsets ----
#define OFF_W1H 0                       // 10240 (float2[10kc][128n][4q])
#define OFF_W1L 10240                   // 10240
#define OFF_W2H 20480                   // 2048  (float2[16kc][16n][4q])
#define OFF_W2L 22528                   // 2048
#define OFF_B1  24576                   // 128
#define OFF_B2  24704                   // 16
#define OFF_R0  24720                   // 6336
#define OFF_R1  31056                   // 6336
#define OFF_H   37392                   // 16896
#define SMEM_FLOATS 54288               // 217152 B

__device__ float g_bufA[Cn*HWn];
__device__ float g_bufB[Cn*HWn];
__device__ float g_w1ph[10240];
__device__ float g_w1pl[10240];
__device__ float g_w2ph[2048];
__device__ float g_w2pl[2048];

__device__ __forceinline__ uint32_t tf32h(float x) {
    uint32_t u;
    asm("cvt.rna.tf32.f32 %0, %1;" : "=r"(u) : "f"(x));
    return u;
}
__device__ __forceinline__ uint32_t smem_u32(const void* p) {
    uint32_t a;
    asm("{ .reg .u64 t; cvta.to.shared.u64 t, %1; cvt.u32.u64 %0, t; }" : "=r"(a) : "l"(p));
    return a;
}
__device__ __forceinline__ void cpa4(uint32_t d, const float* g) {
    asm volatile("cp.async.ca.shared.global [%0], [%1], 4;" :: "r"(d), "l"(g));
}
#define CP_COMMIT() asm volatile("cp.async.commit_group;" ::: "memory")
#define CP_WAIT0()  asm volatile("cp.async.wait_group 0;" ::: "memory")

__device__ __forceinline__ void mma8(float* d,
    uint32_t a0, uint32_t a1, uint32_t a2, uint32_t a3,
    uint32_t b0, uint32_t b1)
{
    asm volatile(
        "mma.sync.aligned.m16n8k8.row.col.f32.tf32.tf32.f32 "
        "{%0,%1,%2,%3}, {%4,%5,%6,%7}, {%8,%9}, {%0,%1,%2,%3};"
        : "+f"(d[0]), "+f"(d[1]), "+f"(d[2]), "+f"(d[3])
        : "r"(a0), "r"(a1), "r"(a2), "r"(a3), "r"(b0), "r"(b1));
}

// ---- weight pre-split + packed-pair relayout ----
// pair layout: f2[idx] = (W[k=kc*8+q], W[k=kc*8+q+4]),  idx = kc*(N*4) + n*4 + q
__global__ void w_setup(const float* __restrict__ W1, const float* __restrict__ W2) {
    int t = threadIdx.x;
    for (int i = t; i < 80*128; i += 256) {     // W1[k][n], k=i>>7
        int k = i >> 7, n = i & 127;
        float v = W1[i];
        float hi = __uint_as_float(tf32h(v));
        int kc = k >> 3, q = k & 3, s2 = (k >> 2) & 1;
        int idx = (kc*512 + n*4 + q)*2 + s2;
        g_w1ph[idx] = hi;
        g_w1pl[idx] = v - hi;
    }
    for (int i = t; i < 128*16; i += 256) {     // W2[k][n], k=i>>4
        int k = i >> 4, n = i & 15;
        float v = W2[i];
        float hi = __uint_as_float(tf32h(v));
        int kc = k >> 3, q = k & 3, s2 = (k >> 2) & 1;
        int idx = (kc*64 + n*4 + q)*2 + s2;
        g_w2ph[idx] = hi;
        g_w2pl[idx] = v - hi;
    }
}

// stage 48 row-segments (16ch x 3 rows) into rows buffer at rb
__device__ __forceinline__ void stage_tile(const float* __restrict__ src,
                                           uint32_t sbase, int rb,
                                           int y, int x0, int w, int lane)
{
    const int ym = (y == 0)    ? 0 : (y - 1);
    const int yp = (y == Hn-1) ? 0 : (y + 1);
    #pragma unroll 1
    for (int s = w; s < 48; s += 8) {
        int c  = s / 3;
        int ri = s - c*3;
        int gy = (ri == 0) ? ym : ((ri == 1) ? y : yp);
        const float* gsrc = src + c*HWn + gy*Wn;
        uint32_t dbase = sbase + (uint32_t)(rb + s*RS) * 4u;
        #pragma unroll
        for (int j0 = 0; j0 < 160; j0 += 32) {
            int j = j0 + lane;
            if (j < 130) {
                int gx = x0 - 1 + j;
                gx = (gx < 0)   ? 0 : gx;
                gx = (gx >= Wn) ? 0 : gx;
                cpa4(dbase + 4u*j, gsrc + gx);
            }
        }
    }
}

__global__ void __launch_bounds__(NTHREADS, 1)
slime_step_mma(const float* __restrict__ src, float* __restrict__ dst,
               const float* __restrict__ gb1, const float* __restrict__ gb2)
{
    extern __shared__ float sm[];
    const uint32_t sbase = smem_u32(sm);
    const int tid = threadIdx.x;
    const int w = tid >> 5, lane = tid & 31;
    const int gr = lane >> 2, q = lane & 3;

    // ---- prologue: packed weights + biases to SMEM ----
    {
        float4* d; const float4* s;
        d = (float4*)(sm + OFF_W1H); s = (const float4*)g_w1ph;
        #pragma unroll
        for (int i = 0; i < 10; i++) d[i*NTHREADS + tid] = s[i*NTHREADS + tid];
        d = (float4*)(sm + OFF_W1L); s = (const float4*)g_w1pl;
        #pragma unroll
        for (int i = 0; i < 10; i++) d[i*NTHREADS + tid] = s[i*NTHREADS + tid];
        d = (float4*)(sm + OFF_W2H); s = (const float4*)g_w2ph;
        #pragma unroll
        for (int i = 0; i < 2; i++) d[i*NTHREADS + tid] = s[i*NTHREADS + tid];
        d = (float4*)(sm + OFF_W2L); s = (const float4*)g_w2pl;
        #pragma unroll
        for (int i = 0; i < 2; i++) d[i*NTHREADS + tid] = s[i*NTHREADS + tid];
        if (tid < 128) sm[OFF_B1 + tid] = gb1[tid];
        if (tid < 16)  sm[OFF_B2 + tid] = gb2[tid];
    }

    // ---- tile-invariant A-fragment offsets ----
    int foA[20];
    #pragma unroll
    for (int kc = 0; kc < 10; kc++)
        #pragma unroll
        for (int s2 = 0; s2 < 2; s2++) {
            int k = kc*8 + q + 4*s2;
            int dd = k >> 4, c = k & 15;
            int ri = (dd == 1) ? 0 : ((dd == 2) ? 2 : 1);
            int dx = (dd == 3) ? -1 : ((dd == 4) ? 1 : 0);
            foA[kc*2 + s2] = (c*3 + ri)*RS + 1 + dx;
        }

    // GEMM1: 8 warps = 2 row-halves x 4 col-quarters (traffic-optimal)
    const int R0 = (w >> 2) * 64, C0 = (w & 3) * 32;
    // GEMM2: warp = 16 rows x 16 cols
    const int R2 = w * 16;

    const float2* W1Hf = (const float2*)(sm + OFF_W1H);
    const float2* W1Lf = (const float2*)(sm + OFF_W1L);
    const float2* W2Hf = (const float2*)(sm + OFF_W2H);
    const float2* W2Lf = (const float2*)(sm + OFF_W2L);
    const float* b1s = sm + OFF_B1;
    const float* b2s = sm + OFF_B2;
    float* Hs = sm + OFF_H;

    const int t0 = blockIdx.x;
    if (t0 < NTILES)
        stage_tile(src, sbase, OFF_R0, t0 >> 2, (t0 & 3) << 7, w, lane);
    CP_COMMIT();
    CP_WAIT0();
    __syncthreads();

    int pb = 0;
    for (int t = t0; t < NTILES; t += GRIDX) {
        const int y = t >> 2, x0 = (t & 3) << 7;
        const int rb  = pb ? OFF_R1 : OFF_R0;
        const int rbn = pb ? OFF_R0 : OFF_R1;
        const float* rcur = sm + rb;

        const int tn = t + GRIDX;
        if (tn < NTILES)
            stage_tile(src, sbase, rbn, tn >> 2, (tn & 3) << 7, w, lane);
        CP_COMMIT();

        // ================= GEMM1: D1 = X @ W1 (+b1), 3xtf32 =================
        float acc[4][4][4];
        #pragma unroll
        for (int nt = 0; nt < 4; nt++) {
            float bz0 = b1s[C0 + nt*8 + 2*q];
            float bz1 = b1s[C0 + nt*8 + 2*q + 1];
            #pragma unroll
            for (int mt = 0; mt < 4; mt++) {
                acc[mt][nt][0] = bz0; acc[mt][nt][1] = bz1;
                acc[mt][nt][2] = bz0; acc[mt][nt][3] = bz1;
            }
        }
        #pragma unroll
        for (int kc = 0; kc < 10; kc++) {
            uint32_t ah[4][4], al[4][4];
            #pragma unroll
            for (int mt = 0; mt < 4; mt++) {
                int r = R0 + mt*16 + gr;
                float v0 = rcur[foA[kc*2+0] + r];
                float v1 = rcur[foA[kc*2+0] + r + 8];
                float v2 = rcur[foA[kc*2+1] + r];
                float v3 = rcur[foA[kc*2+1] + r + 8];
                ah[mt][0] = tf32h(v0); al[mt][0] = __float_as_uint(v0 - __uint_as_float(ah[mt][0]));
                ah[mt][1] = tf32h(v1); al[mt][1] = __float_as_uint(v1 - __uint_as_float(ah[mt][1]));
                ah[mt][2] = tf32h(v2); al[mt][2] = __float_as_uint(v2 - __uint_as_float(ah[mt][2]));
                ah[mt][3] = tf32h(v3); al[mt][3] = __float_as_uint(v3 - __uint_as_float(ah[mt][3]));
            }
            float2 bhv[4], blv[4];
            #pragma unroll
            for (int nt = 0; nt < 4; nt++) {
                int idx = kc*512 + (C0 + nt*8 + gr)*4 + q;
                bhv[nt] = W1Hf[idx];
                blv[nt] = W1Lf[idx];
            }
            // term-major: same-acc dependent MMAs spaced 16 apart
            #pragma unroll
            for (int nt = 0; nt < 4; nt++)
                #pragma unroll
                for (int mt = 0; mt < 4; mt++)
                    mma8(acc[mt][nt], ah[mt][0], ah[mt][1], ah[mt][2], ah[mt][3],
                         __float_as_uint(bhv[nt].x), __float_as_uint(bhv[nt].y));
            #pragma unroll
            for (int nt = 0; nt < 4; nt++)
                #pragma unroll
                for (int mt = 0; mt < 4; mt++)
                    mma8(acc[mt][nt], al[mt][0], al[mt][1], al[mt][2], al[mt][3],
                         __float_as_uint(bhv[nt].x), __float_as_uint(bhv[nt].y));
            #pragma unroll
            for (int nt = 0; nt < 4; nt++)
                #pragma unroll
                for (int mt = 0; mt < 4; mt++)
                    mma8(acc[mt][nt], ah[mt][0], ah[mt][1], ah[mt][2], ah[mt][3],
                         __float_as_uint(blv[nt].x), __float_as_uint(blv[nt].y));
        }
        // ---- H = relu(D1) ----
        #pragma unroll
        for (int mt = 0; mt < 4; mt++) {
            int r = R0 + mt*16 + gr;
            #pragma unroll
            for (int nt = 0; nt < 4; nt++) {
                int c = C0 + nt*8 + 2*q;
                float2 v0 = make_float2(fmaxf(acc[mt][nt][0], 0.0f), fmaxf(acc[mt][nt][1], 0.0f));
                float2 v1 = make_float2(fmaxf(acc[mt][nt][2], 0.0f), fmaxf(acc[mt][nt][3], 0.0f));
                *(float2*)&Hs[r*HS + c]     = v0;
                *(float2*)&Hs[(r+8)*HS + c] = v1;
            }
        }
        __syncthreads();

        // ================= GEMM2: D2 = H @ W2 (+b2), 3xtf32, K-split =================
        float da[2][4], db[2][4];
        #pragma unroll
        for (int nt = 0; nt < 2; nt++) {
            float bz0 = b2s[nt*8 + 2*q], bz1 = b2s[nt*8 + 2*q + 1];
            da[nt][0] = bz0; da[nt][1] = bz1; da[nt][2] = bz0; da[nt][3] = bz1;
            db[nt][0] = 0.f; db[nt][1] = 0.f; db[nt][2] = 0.f; db[nt][3] = 0.f;
        }
        #pragma unroll
        for (int kp = 0; kp < 8; kp++) {
            uint32_t aah[4], aal[4], bah[4], bal[4];
            {
                int r = R2 + gr;
                float v0 = Hs[r*HS     + kp*8 + q];
                float v1 = Hs[(r+8)*HS + kp*8 + q];
                float v2 = Hs[r*HS     + kp*8 + q + 4];
                float v3 = Hs[(r+8)*HS + kp*8 + q + 4];
                aah[0] = tf32h(v0); aal[0] = __float_as_uint(v0 - __uint_as_float(aah[0]));
                aah[1] = tf32h(v1); aal[1] = __float_as_uint(v1 - __uint_as_float(aah[1]));
                aah[2] = tf32h(v2); aal[2] = __float_as_uint(v2 - __uint_as_float(aah[2]));
                aah[3] = tf32h(v3); aal[3] = __float_as_uint(v3 - __uint_as_float(aah[3]));
                float w0 = Hs[r*HS     + (kp+8)*8 + q];
                float w1 = Hs[(r+8)*HS + (kp+8)*8 + q];
                float w2 = Hs[r*HS     + (kp+8)*8 + q + 4];
                float w3 = Hs[(r+8)*HS + (kp+8)*8 + q + 4];
                bah[0] = tf32h(w0); bal[0] = __float_as_uint(w0 - __uint_as_float(bah[0]));
                bah[1] = tf32h(w1); bal[1] = __float_as_uint(w1 - __uint_as_float(bah[1]));
                bah[2] = tf32h(w2); bal[2] = __float_as_uint(w2 - __uint_as_float(bah[2]));
                bah[3] = tf32h(w3); bal[3] = __float_as_uint(w3 - __uint_as_float(bah[3]));
            }
            #pragma unroll
            for (int nt = 0; nt < 2; nt++) {
                int ia = kp*64 + (nt*8 + gr)*4 + q;
                int ib = (kp+8)*64 + (nt*8 + gr)*4 + q;
                float2 wha = W2Hf[ia], wla = W2Lf[ia];
                float2 whb = W2Hf[ib], wlb = W2Lf[ib];
                mma8(da[nt], aah[0], aah[1], aah[2], aah[3], __float_as_uint(wha.x), __float_as_uint(wha.y));
                mma8(db[nt], bah[0], bah[1], bah[2], bah[3], __float_as_uint(whb.x), __float_as_uint(whb.y));
                mma8(da[nt], aal[0], aal[1], aal[2], aal[3], __float_as_uint(wha.x), __float_as_uint(wha.y));
                mma8(db[nt], bal[0], bal[1], bal[2], bal[3], __float_as_uint(whb.x), __float_as_uint(whb.y));
                mma8(da[nt], aah[0], aah[1], aah[2], aah[3], __float_as_uint(wla.x), __float_as_uint(wla.y));
                mma8(db[nt], bah[0], bah[1], bah[2], bah[3], __float_as_uint(wlb.x), __float_as_uint(wlb.y));
            }
        }

        // ---- output: s + delta (channel 0 snapshot-restored) ----
        {
            int px0  = R2 + gr;
            int pix0 = y*Wn + x0 + px0;
            #pragma unroll
            for (int nt = 0; nt < 2; nt++) {
                #pragma unroll
                for (int jj = 0; jj < 4; jj++) {
                    int c   = nt*8 + 2*q + (jj & 1);
                    int px  = px0  + ((jj >= 2) ? 8 : 0);
                    int pix = pix0 + ((jj >= 2) ? 8 : 0);
                    float center = rcur[(c*3 + 1)*RS + 1 + px];
                    float vout = (c == 0) ? center : (center + da[nt][jj] + db[nt][jj]);
                    dst[c*HWn + pix] = vout;
                }
            }
        }

        CP_WAIT0();
        __syncthreads();
        pb ^= 1;
    }
}

extern "C" void kernel_launch(void* const* d_in, const int* in_sizes, int n_in,
                              void* d_out, int out_size)
{
    const float* state = (const float*)d_in[0];
    const float* W1    = (const float*)d_in[1];
    const float* b1    = (const float*)d_in[2];
    const float* W2    = (const float*)d_in[3];
    const float* b2    = (const float*)d_in[4];
    float* out = (float*)d_out;

    cudaFuncSetAttribute(slime_step_mma,
                         cudaFuncAttributeMaxDynamicSharedMemorySize,
                         SMEM_FLOATS * (int)sizeof(float));

    float *bufA, *bufB;
    cudaGetSymbolAddress((void**)&bufA, g_bufA);
    cudaGetSymbolAddress((void**)&bufB, g_bufB);

    w_setup<<<1, 256>>>(W1, W2);

    const float* cur = state;
    for (int s = 0; s < NSTEPS; s++) {
        float* dstp = (s == NSTEPS-1) ? out : ((s & 1) ? bufB : bufA);
        slime_step_mma<<<GRIDX, NTHREADS, SMEM_FLOATS*sizeof(float)>>>(cur, dstp, b1, b2);
        cur = dstp;
    }
}